// round 6
// baseline (speedup 1.0000x reference)
#include <cuda_runtime.h>
#include <math.h>

// DCTBlur: out[b,c,k,l] = damp(b,k,l) * (D @ X_{b,c} @ D^T)[k,l], N=512.
//  - D[k, N-1-n] = (-1)^k D[k,n] -> even/odd half-GEMMs with K=256 (2x FLOPs saved).
//  - damp separable: exp(-(fk^2+fl^2)*tt) = dv[b,k]*dv[b,l], fused in stage-2 epilogue.
//  - Two-pass batched fp32 SGEMM (128x128x8, 8x8/thread, double-buffered smem).
//  - Init transcendentals evaluated in double on fp32-rounded angles (matches the
//    f32 reference's rounding, immune to --use_fast_math approximations).

#define NN   512
#define HH   256
#define IMGS 192
#define NB   64

__device__ float g_T[IMGS * NN * NN];   // stage-1 scratch (201 MB)
__device__ float g_De[HH * HH];         // De[k2][h] = D[2k2  ][h], h<256
__device__ float g_Do[HH * HH];         // Do[k2][h] = D[2k2+1][h], h<256
__device__ float g_dv[NB * NN];         // dv[b][i] = exp(-(pi*i/N)^2 * tt_b)

// ---------------------------------------------------------------------------
// Init kernels. Angles computed in f32 with the reference's op order
// ((pi*(n+0.5)) * k) / N, then transcendental in double (fast-math-proof).
// ---------------------------------------------------------------------------
__global__ void k_init_D() {
    int idx = blockIdx.x * blockDim.x + threadIdx.x;
    if (idx >= HH * HH) return;
    int k2 = idx / HH;
    int h  = idx & (HH - 1);
    float p  = (float)M_PI * ((float)h + 0.5f);           // f32, ref order
    float ae = p * (float)(2 * k2)     / (float)NN;       // f32, ref order
    float ao = p * (float)(2 * k2 + 1) / (float)NN;
    float se = (k2 == 0) ? sqrtf(1.0f / (float)NN) : sqrtf(2.0f / (float)NN);
    float so = sqrtf(2.0f / (float)NN);
    g_De[idx] = se * (float)cos((double)ae);
    g_Do[idx] = so * (float)cos((double)ao);
}

__global__ void k_init_damp(const float* __restrict__ t) {
    int idx = blockIdx.x * blockDim.x + threadIdx.x;
    if (idx >= NB * NN) return;
    int b = idx / NN;
    int i = idx & (NN - 1);
    double tt = 0.5 * pow(40.0, (double)t[b]);
    tt = tt * tt * 0.5;
    float f = ((float)M_PI * (float)i) / (float)NN;       // f32, ref order
    g_dv[idx] = (float)exp(-(double)(f * f) * tt);
}

// ---------------------------------------------------------------------------
// Stage 1: T[img][2*k2+p][w] = sum_{h<256} Dp[k2][h]*(x[h][w] + s*x[511-h][w])
//   M = 256 (k2), N = 512 (w), K = 256 (h).  grid = (4, 2, IMGS*2)
// ---------------------------------------------------------------------------
__global__ __launch_bounds__(256, 2) void k_gemm1(const float* __restrict__ x)
{
    const int z      = blockIdx.z;
    const int img    = z >> 1;
    const int parity = z & 1;
    const float* __restrict__ A  = parity ? g_Do : g_De;      // [256][256]
    const float* __restrict__ X  = x   + (size_t)img * NN * NN;
    float*       __restrict__ To = g_T + (size_t)img * NN * NN;
    const float sgn = parity ? -1.0f : 1.0f;

    const int mBase = blockIdx.y << 7;
    const int nBase = blockIdx.x << 7;
    const int tid   = threadIdx.x;

    __shared__ float As[2][8][128];   // As[kk][m] (A transposed)
    __shared__ float Bs[2][8][128];   // Bs[kk][n]

    const int ar = tid >> 1,  ac = (tid & 1)  << 2;   // A loader: row, k-offset
    const int bk = tid >> 5,  bw = (tid & 31) << 2;   // B loader: k-row, n-offset
    const int my = (tid >> 4) << 3, nx = (tid & 15) << 3;

    float acc[8][8];
    #pragma unroll
    for (int i = 0; i < 8; i++)
        #pragma unroll
        for (int j = 0; j < 8; j++) acc[i][j] = 0.0f;

    float4 pa, pb;
    pa = *(const float4*)&A[(mBase + ar) * HH + ac];
    {
        const float4 u = *(const float4*)&X[bk * NN + nBase + bw];
        const float4 v = *(const float4*)&X[(NN - 1 - bk) * NN + nBase + bw];
        pb = make_float4(u.x + sgn * v.x, u.y + sgn * v.y,
                         u.z + sgn * v.z, u.w + sgn * v.w);
    }

    for (int kt = 0; kt < HH / 8; kt++) {
        const int buf = kt & 1;
        As[buf][ac + 0][ar] = pa.x; As[buf][ac + 1][ar] = pa.y;
        As[buf][ac + 2][ar] = pa.z; As[buf][ac + 3][ar] = pa.w;
        *(float4*)&Bs[buf][bk][bw] = pb;
        __syncthreads();

        if (kt + 1 < HH / 8) {
            const int kB = (kt + 1) << 3;
            pa = *(const float4*)&A[(mBase + ar) * HH + kB + ac];
            const float4 u = *(const float4*)&X[(kB + bk) * NN + nBase + bw];
            const float4 v = *(const float4*)&X[(NN - 1 - kB - bk) * NN + nBase + bw];
            pb = make_float4(u.x + sgn * v.x, u.y + sgn * v.y,
                             u.z + sgn * v.z, u.w + sgn * v.w);
        }

        #pragma unroll
        for (int kk = 0; kk < 8; kk++) {
            const float4 a0 = *(const float4*)&As[buf][kk][my];
            const float4 a1 = *(const float4*)&As[buf][kk][my + 4];
            const float4 b0 = *(const float4*)&Bs[buf][kk][nx];
            const float4 b1 = *(const float4*)&Bs[buf][kk][nx + 4];
            const float a[8] = {a0.x, a0.y, a0.z, a0.w, a1.x, a1.y, a1.z, a1.w};
            const float b[8] = {b0.x, b0.y, b0.z, b0.w, b1.x, b1.y, b1.z, b1.w};
            #pragma unroll
            for (int i = 0; i < 8; i++)
                #pragma unroll
                for (int j = 0; j < 8; j++)
                    acc[i][j] += a[i] * b[j];
        }
    }

    #pragma unroll
    for (int i = 0; i < 8; i++) {
        const int krow = ((mBase + my + i) << 1) + parity;
        float* o = To + krow * NN + nBase + nx;
        *(float4*)(o)     = make_float4(acc[i][0], acc[i][1], acc[i][2], acc[i][3]);
        *(float4*)(o + 4) = make_float4(acc[i][4], acc[i][5], acc[i][6], acc[i][7]);
    }
}

// ---------------------------------------------------------------------------
// Stage 2: out[img][k][2*l2+p] = dv[b][k]*dv[b][l] *
//            sum_{w<256} (T[k][w] + s*T[k][511-w]) * Dp[l2][w]
//   M = 512 (k), N = 256 (l2), K = 256 (w).  grid = (2, 4, IMGS*2)
// ---------------------------------------------------------------------------
__global__ __launch_bounds__(256, 2) void k_gemm2(float* __restrict__ out)
{
    const int z      = blockIdx.z;
    const int img    = z >> 1;
    const int parity = z & 1;
    const float* __restrict__ Dp = parity ? g_Do : g_De;       // [256][256]
    const float* __restrict__ Ti = g_T + (size_t)img * NN * NN;
    float*       __restrict__ O  = out + (size_t)img * NN * NN;
    const float sgn = parity ? -1.0f : 1.0f;

    const int mBase = blockIdx.y << 7;
    const int nBase = blockIdx.x << 7;
    const int tid   = threadIdx.x;

    __shared__ float As[2][8][128];
    __shared__ float Bs[2][8][128];

    const int ar = tid >> 1, ac = (tid & 1) << 2;   // A loader (T rows)
    const int bn = tid >> 1, bc = (tid & 1) << 2;   // B loader (Dp rows)
    const int my = (tid >> 4) << 3, nx = (tid & 15) << 3;

    float acc[8][8];
    #pragma unroll
    for (int i = 0; i < 8; i++)
        #pragma unroll
        for (int j = 0; j < 8; j++) acc[i][j] = 0.0f;

    float4 pa, pb;
    {
        const float4 u = *(const float4*)&Ti[(mBase + ar) * NN + ac];
        const float4 v = *(const float4*)&Ti[(mBase + ar) * NN + (NN - 4 - ac)];
        pa = make_float4(u.x + sgn * v.w, u.y + sgn * v.z,
                         u.z + sgn * v.y, u.w + sgn * v.x);
        pb = *(const float4*)&Dp[(nBase + bn) * HH + bc];
    }

    for (int kt = 0; kt < HH / 8; kt++) {
        const int buf = kt & 1;
        As[buf][ac + 0][ar] = pa.x; As[buf][ac + 1][ar] = pa.y;
        As[buf][ac + 2][ar] = pa.z; As[buf][ac + 3][ar] = pa.w;
        Bs[buf][bc + 0][bn] = pb.x; Bs[buf][bc + 1][bn] = pb.y;
        Bs[buf][bc + 2][bn] = pb.z; Bs[buf][bc + 3][bn] = pb.w;
        __syncthreads();

        if (kt + 1 < HH / 8) {
            const int kB = (kt + 1) << 3;
            const float4 u = *(const float4*)&Ti[(mBase + ar) * NN + kB + ac];
            const float4 v = *(const float4*)&Ti[(mBase + ar) * NN + (NN - 4 - kB - ac)];
            pa = make_float4(u.x + sgn * v.w, u.y + sgn * v.z,
                             u.z + sgn * v.y, u.w + sgn * v.x);
            pb = *(const float4*)&Dp[(nBase + bn) * HH + kB + bc];
        }

        #pragma unroll
        for (int kk = 0; kk < 8; kk++) {
            const float4 a0 = *(const float4*)&As[buf][kk][my];
            const float4 a1 = *(const float4*)&As[buf][kk][my + 4];
            const float4 b0 = *(const float4*)&Bs[buf][kk][nx];
            const float4 b1 = *(const float4*)&Bs[buf][kk][nx + 4];
            const float a[8] = {a0.x, a0.y, a0.z, a0.w, a1.x, a1.y, a1.z, a1.w};
            const float b[8] = {b0.x, b0.y, b0.z, b0.w, b1.x, b1.y, b1.z, b1.w};
            #pragma unroll
            for (int i = 0; i < 8; i++)
                #pragma unroll
                for (int j = 0; j < 8; j++)
                    acc[i][j] += a[i] * b[j];
        }
    }

    const int b = img / 3;
    const float* __restrict__ dvb = g_dv + b * NN;
    #pragma unroll
    for (int i = 0; i < 8; i++) {
        const int k  = mBase + my + i;
        const float dk = dvb[k];
        #pragma unroll
        for (int j = 0; j < 8; j++) {
            const int l = ((nBase + nx + j) << 1) + parity;
            O[k * NN + l] = acc[i][j] * dk * dvb[l];
        }
    }
}

// ---------------------------------------------------------------------------
extern "C" void kernel_launch(void* const* d_in, const int* in_sizes, int n_in,
                              void* d_out, int out_size)
{
    const float* x   = (const float*)d_in[0];   // [64,3,512,512] f32
    const float* t   = (const float*)d_in[1];   // [64] f32
    float*       out = (float*)d_out;           // [64,3,512,512] f32

    k_init_D<<<(HH * HH + 255) / 256, 256>>>();
    k_init_damp<<<(NB * NN + 255) / 256, 256>>>(t);
    k_gemm1<<<dim3(4, 2, IMGS * 2), 256>>>(x);
    k_gemm2<<<dim3(2, 4, IMGS * 2), 256>>>(out);
}

// round 16
// speedup vs baseline: 1.1062x; 1.1062x over previous
#include <cuda_runtime.h>
#include <cuda_bf16.h>
#include <math.h>
#include <stdint.h>

// DCTBlur via mma.sync (m16n8k16 bf16, sm_80-baseline PTX — no 'a'-features;
// the harness PTX target is compute_103 which rejects tcgen05).
// out[b,c,k,l] = damp(b,k,l) * (D @ X @ D^T)[k,l], N=512.
// Stage 1 (folded, K=256): T[2k2+p][w] = sum_h Dp[k2][h]*(x[h][w] +- x[511-h][w])
// Stage 2 (unfolded, K=512): out[k][l] = dv[k]*dv[l] * sum_w T[k][w]*Dfull[l][w]
// fp32 operands split into bf16 hi+lo; 3 MMAs (HH, LH, HL), fp32 accumulators.

#define NN   512
#define HH   256
#define IMGS 192
#define NB   64

__device__ float g_T[(size_t)IMGS * NN * NN];   // stage-1 result, 201 MB
__device__ float g_De[HH * HH];                 // D[2k2  ][h]
__device__ float g_Do[HH * HH];                 // D[2k2+1][h]
__device__ float g_Dfull[NN * NN];              // D[l][w]
__device__ float g_dv[NB * NN];                 // separable damp vectors

// mma.sync m16n8k16 row.col f32.bf16.bf16.f32 (sm_80+, baseline PTX)
#define MMA_BF16(c, a, b)                                                        \
    asm volatile("mma.sync.aligned.m16n8k16.row.col.f32.bf16.bf16.f32 "          \
        "{%0,%1,%2,%3}, {%4,%5,%6,%7}, {%8,%9}, {%0,%1,%2,%3};"                  \
        : "+f"((c)[0]), "+f"((c)[1]), "+f"((c)[2]), "+f"((c)[3])                 \
        : "r"((a)[0]), "r"((a)[1]), "r"((a)[2]), "r"((a)[3]),                    \
          "r"((b)[0]), "r"((b)[1]))

// Padded smem: rows of 32 bf16 = 16 words + 2 pad = 18 words (conflict-free frags)
#define RSTRIDE 18

__device__ __forceinline__ uint32_t pack_bf16x2(float x, float y) {
    __nv_bfloat162 v(__float2bfloat16(x), __float2bfloat16(y));
    return *(uint32_t*)&v;
}

// ---------------- init kernels (fast-math-proof transcendentals) ------------
__global__ void k_init_D() {
    int idx = blockIdx.x * blockDim.x + threadIdx.x;
    if (idx >= HH * HH) return;
    int k2 = idx / HH;
    int h  = idx & (HH - 1);
    float p  = (float)M_PI * ((float)h + 0.5f);
    float ae = p * (float)(2 * k2)     / (float)NN;
    float ao = p * (float)(2 * k2 + 1) / (float)NN;
    float se = (k2 == 0) ? sqrtf(1.0f / (float)NN) : sqrtf(2.0f / (float)NN);
    float so = sqrtf(2.0f / (float)NN);
    g_De[idx] = se * (float)cos((double)ae);
    g_Do[idx] = so * (float)cos((double)ao);
}
__global__ void k_init_Dfull() {
    int idx = blockIdx.x * blockDim.x + threadIdx.x;
    if (idx >= NN * NN) return;
    int l = idx / NN;
    int w = idx & (NN - 1);
    float p = (float)M_PI * ((float)w + 0.5f);
    float a = p * (float)l / (float)NN;
    float s = (l == 0) ? sqrtf(1.0f / (float)NN) : sqrtf(2.0f / (float)NN);
    g_Dfull[idx] = s * (float)cos((double)a);
}
__global__ void k_init_damp(const float* __restrict__ t) {
    int idx = blockIdx.x * blockDim.x + threadIdx.x;
    if (idx >= NB * NN) return;
    int b = idx / NN;
    int i = idx & (NN - 1);
    double tt = 0.5 * pow(40.0, (double)t[b]);
    tt = tt * tt * 0.5;
    float f = ((float)M_PI * (float)i) / (float)NN;
    g_dv[idx] = (float)exp(-(double)(f * f) * tt);
}

// ---------------- smem tile loader: fp32 -> bf16 hi/lo, [R rows][32 k] ------
template <int R>
__device__ __forceinline__ void load_tile(uint32_t* hi, uint32_t* lo,
                                          const float* __restrict__ src,
                                          int row0, int col0, int ld, int tid)
{
    #pragma unroll
    for (int it = 0; it < R * 8 / 256; ++it) {
        int q  = it * 256 + tid;
        int r  = q >> 3;          // row
        int c4 = q & 7;           // float4 index (8 per 32-float row)
        const float4 u = *(const float4*)&src[(size_t)(row0 + r) * ld + col0 + 4 * c4];
        float hx = __bfloat162float(__float2bfloat16(u.x));
        float hy = __bfloat162float(__float2bfloat16(u.y));
        float hz = __bfloat162float(__float2bfloat16(u.z));
        float hw = __bfloat162float(__float2bfloat16(u.w));
        int base = r * RSTRIDE + c4 * 2;
        hi[base]     = pack_bf16x2(u.x, u.y);
        hi[base + 1] = pack_bf16x2(u.z, u.w);
        lo[base]     = pack_bf16x2(u.x - hx, u.y - hy);
        lo[base + 1] = pack_bf16x2(u.z - hz, u.w - hw);
    }
}

// Stage-1 B: fold + transpose. B[w_local(64)][h_local(32)] = x[h][w] + sgn*x[511-h][w]
__device__ __forceinline__ void load_Bfold(uint32_t* hi, uint32_t* lo,
                                           const float* __restrict__ X,
                                           int hBase, int nBase, float sgn, int tid)
{
    __nv_bfloat16* bh = (__nv_bfloat16*)hi;
    __nv_bfloat16* bl = (__nv_bfloat16*)lo;
    #pragma unroll
    for (int it = 0; it < 2; ++it) {
        int q  = it * 256 + tid;          // 512 tasks: 32 h x 16 w4
        int h  = q >> 4;                  // local h 0..31
        int w4 = q & 15;                  // float4 over 64 w
        int hg = hBase + h;
        const float4 u = *(const float4*)&X[(size_t)hg * NN + nBase + 4 * w4];
        const float4 v = *(const float4*)&X[(size_t)(NN - 1 - hg) * NN + nBase + 4 * w4];
        float y[4] = {u.x + sgn * v.x, u.y + sgn * v.y, u.z + sgn * v.z, u.w + sgn * v.w};
        #pragma unroll
        for (int e = 0; e < 4; ++e) {
            int wl = 4 * w4 + e;
            __nv_bfloat16 hbf = __float2bfloat16(y[e]);
            __nv_bfloat16 lbf = __float2bfloat16(y[e] - __bfloat162float(hbf));
            bh[wl * (2 * RSTRIDE) + h] = hbf;   // 2*RSTRIDE bf16 per row
            bl[wl * (2 * RSTRIDE) + h] = lbf;
        }
    }
}

// ---------------- fragment helpers ------------------------------------------
__device__ __forceinline__ void load_afrag(uint32_t* a, const uint32_t* As,
                                           int rbase, int kw, int g, int tig)
{
    int ra = (rbase + g) * RSTRIDE + kw + tig;
    int rb = ra + 8 * RSTRIDE;
    a[0] = As[ra];     a[1] = As[rb];
    a[2] = As[ra + 4]; a[3] = As[rb + 4];
}
__device__ __forceinline__ void load_bfrag(uint32_t* b, const uint32_t* Bs,
                                           int nbase, int kw, int g, int tig)
{
    int nb = (nbase + g) * RSTRIDE + kw + tig;
    b[0] = Bs[nb];
    b[1] = Bs[nb + 4];
}

// ---------------- stage 1: T = Dp @ Yfold^T, CTA 128m x 64n, K=256 ----------
__global__ __launch_bounds__(256, 2) void k_mma1(const float* __restrict__ x)
{
    __shared__ uint32_t As_hi[128 * RSTRIDE], As_lo[128 * RSTRIDE];
    __shared__ uint32_t Bs_hi[64 * RSTRIDE],  Bs_lo[64 * RSTRIDE];

    const int tid  = threadIdx.x;
    const int wid  = tid >> 5;
    const int lane = tid & 31;
    const int g    = lane >> 2, tig = lane & 3;
    const int mW   = (wid & 1) * 64;   // 2 warps in m
    const int nW   = (wid >> 1) * 16;  // 4 warps in n

    const int img    = blockIdx.z >> 1;
    const int parity = blockIdx.z & 1;
    const float* __restrict__ Dp = parity ? g_Do : g_De;
    const float sgn = parity ? -1.0f : 1.0f;
    const float* __restrict__ X = x + (size_t)img * NN * NN;
    const int mBase = blockIdx.y << 7;   // k2 tile (2 blocks x 128)
    const int nBase = blockIdx.x << 6;   // w tile (8 blocks x 64)

    float acc[4][2][4];
    #pragma unroll
    for (int i = 0; i < 4; ++i)
        #pragma unroll
        for (int j = 0; j < 2; ++j)
            #pragma unroll
            for (int e = 0; e < 4; ++e) acc[i][j][e] = 0.0f;

    for (int ch = 0; ch < 8; ++ch) {
        __syncthreads();
        load_tile<128>(As_hi, As_lo, Dp, mBase, ch * 32, HH, tid);
        load_Bfold(Bs_hi, Bs_lo, X, ch * 32, nBase, sgn, tid);
        __syncthreads();

        #pragma unroll
        for (int ks = 0; ks < 2; ++ks) {
            const int kw = ks * 8;
            uint32_t bh[2][2], bl[2][2];
            #pragma unroll
            for (int j = 0; j < 2; ++j) {
                load_bfrag(bh[j], Bs_hi, nW + j * 8, kw, g, tig);
                load_bfrag(bl[j], Bs_lo, nW + j * 8, kw, g, tig);
            }
            #pragma unroll
            for (int i = 0; i < 4; ++i) {
                uint32_t ah[4], al[4];
                load_afrag(ah, As_hi, mW + i * 16, kw, g, tig);
                load_afrag(al, As_lo, mW + i * 16, kw, g, tig);
                #pragma unroll
                for (int j = 0; j < 2; ++j) {
                    MMA_BF16(acc[i][j], ah, bh[j]);
                    MMA_BF16(acc[i][j], al, bh[j]);
                    MMA_BF16(acc[i][j], ah, bl[j]);
                }
            }
        }
    }

    float* __restrict__ To = g_T + (size_t)img * NN * NN;
    #pragma unroll
    for (int i = 0; i < 4; ++i) {
        const int r0  = mW + i * 16 + g;
        const int ka  = mBase + r0;
        const int rowA = ((ka) << 1) + parity;
        const int rowB = ((ka + 8) << 1) + parity;
        #pragma unroll
        for (int j = 0; j < 2; ++j) {
            const int col = nBase + nW + j * 8 + tig * 2;
            *(float2*)&To[(size_t)rowA * NN + col] = make_float2(acc[i][j][0], acc[i][j][1]);
            *(float2*)&To[(size_t)rowB * NN + col] = make_float2(acc[i][j][2], acc[i][j][3]);
        }
    }
}

// ---------------- stage 2: out = (T @ Dfull^T)*damp, CTA 128m x 64n, K=512 --
__global__ __launch_bounds__(256, 2) void k_mma2(float* __restrict__ out)
{
    __shared__ uint32_t As_hi[128 * RSTRIDE], As_lo[128 * RSTRIDE];
    __shared__ uint32_t Bs_hi[64 * RSTRIDE],  Bs_lo[64 * RSTRIDE];

    const int tid  = threadIdx.x;
    const int wid  = tid >> 5;
    const int lane = tid & 31;
    const int g    = lane >> 2, tig = lane & 3;
    const int mW   = (wid & 1) * 64;
    const int nW   = (wid >> 1) * 16;

    const int img   = blockIdx.z;
    const float* __restrict__ Ti = g_T + (size_t)img * NN * NN;
    const int mBase = blockIdx.y << 7;   // k tile (4 blocks)
    const int nBase = blockIdx.x << 6;   // l tile (8 blocks)

    float acc[4][2][4];
    #pragma unroll
    for (int i = 0; i < 4; ++i)
        #pragma unroll
        for (int j = 0; j < 2; ++j)
            #pragma unroll
            for (int e = 0; e < 4; ++e) acc[i][j][e] = 0.0f;

    for (int ch = 0; ch < 16; ++ch) {
        __syncthreads();
        load_tile<128>(As_hi, As_lo, Ti,      mBase, ch * 32, NN, tid);
        load_tile<64> (Bs_hi, Bs_lo, g_Dfull, nBase, ch * 32, NN, tid);
        __syncthreads();

        #pragma unroll
        for (int ks = 0; ks < 2; ++ks) {
            const int kw = ks * 8;
            uint32_t bh[2][2], bl[2][2];
            #pragma unroll
            for (int j = 0; j < 2; ++j) {
                load_bfrag(bh[j], Bs_hi, nW + j * 8, kw, g, tig);
                load_bfrag(bl[j], Bs_lo, nW + j * 8, kw, g, tig);
            }
            #pragma unroll
            for (int i = 0; i < 4; ++i) {
                uint32_t ah[4], al[4];
                load_afrag(ah, As_hi, mW + i * 16, kw, g, tig);
                load_afrag(al, As_lo, mW + i * 16, kw, g, tig);
                #pragma unroll
                for (int j = 0; j < 2; ++j) {
                    MMA_BF16(acc[i][j], ah, bh[j]);
                    MMA_BF16(acc[i][j], al, bh[j]);
                    MMA_BF16(acc[i][j], ah, bl[j]);
                }
            }
        }
    }

    const int b = img / 3;
    const float* __restrict__ dvb = g_dv + b * NN;
    float* __restrict__ O = out + (size_t)img * NN * NN;
    #pragma unroll
    for (int i = 0; i < 4; ++i) {
        const int rA = mBase + mW + i * 16 + g;
        const int rB = rA + 8;
        const float dA = dvb[rA], dB = dvb[rB];
        #pragma unroll
        for (int j = 0; j < 2; ++j) {
            const int col = nBase + nW + j * 8 + tig * 2;
            const float d0 = dvb[col], d1 = dvb[col + 1];
            *(float2*)&O[(size_t)rA * NN + col] =
                make_float2(acc[i][j][0] * dA * d0, acc[i][j][1] * dA * d1);
            *(float2*)&O[(size_t)rB * NN + col] =
                make_float2(acc[i][j][2] * dB * d0, acc[i][j][3] * dB * d1);
        }
    }
}

// ---------------------------------------------------------------------------
extern "C" void kernel_launch(void* const* d_in, const int* in_sizes, int n_in,
                              void* d_out, int out_size)
{
    const float* x   = (const float*)d_in[0];   // [64,3,512,512] f32
    const float* t   = (const float*)d_in[1];   // [64] f32
    float*       out = (float*)d_out;           // [64,3,512,512] f32

    k_init_D<<<(HH * HH + 255) / 256, 256>>>();
    k_init_Dfull<<<(NN * NN + 255) / 256, 256>>>();
    k_init_damp<<<(NB * NN + 255) / 256, 256>>>(t);
    k_mma1<<<dim3(8, 2, IMGS * 2), 256>>>(x);
    k_mma2<<<dim3(8, 4, IMGS), 256>>>(out);
}